// round 1
// baseline (speedup 1.0000x reference)
#include <cuda_runtime.h>

#define NN 100000
#define NE 1600000
#define TOT (NE + NN)
#define HD 128

// ---------------- scratch (device globals; no allocation allowed) ------------
__device__ float4 g_h0[NN * 32];   // h0 = relu(x@W1+b1)
__device__ float4 g_hA[NN * 32];
__device__ float4 g_hB[NN * 32];
__device__ int    g_cnt[NN];
__device__ int    g_fill[NN];
__device__ float  g_dinv[NN];
__device__ int    g_rowptr[NN + 1];
__device__ int    g_col[TOT];
__device__ float  g_w[TOT];
__device__ int    g_bsum[64];
__device__ int    g_boff[64];
__device__ int    g_is64;

// ---------------- edge dtype detection (int64 vs int32) ---------------------
__global__ void detect64(const int* ei32) {
    int lane = threadIdx.x;
    int orv = 0;
    for (int i = lane; i < 1024; i += 32) orv |= ei32[2 * i + 1];
    #pragma unroll
    for (int off = 16; off; off >>= 1) orv |= __shfl_xor_sync(0xFFFFFFFFu, orv, off);
    if (lane == 0) g_is64 = (orv == 0) ? 1 : 0;
}

__device__ __forceinline__ int edge_src(const void* ei, int e) {
    if (g_is64) return (int)((const long long*)ei)[e];
    return ((const int*)ei)[e];
}
__device__ __forceinline__ int edge_dst(const void* ei, int e) {
    if (g_is64) return (int)((const long long*)ei)[NE + e];
    return ((const int*)ei)[NE + e];
}

// ---------------- degree / normalization ------------------------------------
__global__ void init_deg() {
    int n = blockIdx.x * blockDim.x + threadIdx.x;
    if (n < NN) { g_cnt[n] = 1; g_fill[n] = 0; }  // 1 = self loop
}

__global__ void hist(const void* __restrict__ ei) {
    int e = blockIdx.x * blockDim.x + threadIdx.x;
    if (e < NE) atomicAdd(&g_cnt[edge_dst(ei, e)], 1);
}

__global__ void dinv_k() {
    int n = blockIdx.x * blockDim.x + threadIdx.x;
    if (n < NN) g_dinv[n] = rsqrtf((float)g_cnt[n]);
}

// ---------------- exclusive scan of g_cnt -> g_rowptr (3 kernels) ------------
// 256 threads/block, 8 elems/thread -> 2048 elems/block, 49 blocks for 100000.
__global__ void scan1() {
    __shared__ int sh[256];
    int tid = threadIdx.x;
    int base = blockIdx.x * 2048 + tid * 8;
    int v[8];
    int s = 0;
    #pragma unroll
    for (int i = 0; i < 8; i++) {
        int idx = base + i;
        v[i] = (idx < NN) ? g_cnt[idx] : 0;
        s += v[i];
    }
    sh[tid] = s;
    __syncthreads();
    // inclusive Hillis-Steele over 256 thread sums
    for (int off = 1; off < 256; off <<= 1) {
        int t = (tid >= off) ? sh[tid - off] : 0;
        __syncthreads();
        sh[tid] += t;
        __syncthreads();
    }
    int run = sh[tid] - s;  // exclusive prefix within block
    #pragma unroll
    for (int i = 0; i < 8; i++) {
        int idx = base + i;
        if (idx < NN) g_rowptr[idx] = run;
        run += v[i];
    }
    if (tid == 255) g_bsum[blockIdx.x] = sh[255];
}

__global__ void scan2(int nblocks) {
    int acc = 0;
    for (int i = 0; i < nblocks; i++) { g_boff[i] = acc; acc += g_bsum[i]; }
}

__global__ void scan3() {
    int idx = blockIdx.x * blockDim.x + threadIdx.x;
    if (idx < NN) g_rowptr[idx] += g_boff[idx >> 11];
    if (idx == 0) g_rowptr[NN] = TOT;
}

// ---------------- CSR scatter (edges + self loops) ---------------------------
__global__ void scatter(const void* __restrict__ ei) {
    int e = blockIdx.x * blockDim.x + threadIdx.x;
    if (e < NE) {
        int s = edge_src(ei, e);
        int d = edge_dst(ei, e);
        int pos = g_rowptr[d] + atomicAdd(&g_fill[d], 1);
        g_col[pos] = s;
        g_w[pos] = g_dinv[s] * g_dinv[d];
    } else if (e < TOT) {
        int n = e - NE;
        int pos = g_rowptr[n] + atomicAdd(&g_fill[n], 1);
        g_col[pos] = n;
        float di = g_dinv[n];
        g_w[pos] = di * di;
    }
}

// ---------------- 128-tile fp32 SGEMM: out = [relu](X@W + b) -----------------
// Block: 256 threads, tile 128 rows x 128 cols, K chunked by 32.
__global__ __launch_bounds__(256) void gemm128(
    const float* __restrict__ X, const float* __restrict__ Wm,
    const float* __restrict__ bias, float* __restrict__ out, int relu)
{
    __shared__ float As[128][33];   // [row][k], pad 33 to kill bank conflicts
    __shared__ float Bs[32][128];   // [k][col]

    int tid = threadIdx.x;
    int tx = tid & 15;          // col microtile index (8 cols each)
    int ty = tid >> 4;          // row microtile index (8 rows each)
    int rowBase = blockIdx.x * 128;

    float acc[64];
    #pragma unroll
    for (int i = 0; i < 64; i++) acc[i] = 0.0f;

    for (int kc = 0; kc < 4; kc++) {
        // load A tile: 128 rows x 32 k   (1024 float4 slots)
        #pragma unroll
        for (int l = 0; l < 4; l++) {
            int idx = tid + l * 256;       // 0..1023
            int r  = idx >> 3;             // 0..127
            int kq = idx & 7;              // float4 within the 32-k chunk
            float4 v = make_float4(0.f, 0.f, 0.f, 0.f);
            int row = rowBase + r;
            if (row < NN)
                v = reinterpret_cast<const float4*>(X)[row * 32 + kc * 8 + kq];
            As[r][kq * 4 + 0] = v.x;
            As[r][kq * 4 + 1] = v.y;
            As[r][kq * 4 + 2] = v.z;
            As[r][kq * 4 + 3] = v.w;
        }
        // load B tile: 32 k x 128 cols
        #pragma unroll
        for (int l = 0; l < 4; l++) {
            int idx = tid + l * 256;       // 0..1023 float4 slots
            int k  = idx >> 5;
            int cq = idx & 31;
            reinterpret_cast<float4*>(&Bs[k][0])[cq] =
                reinterpret_cast<const float4*>(Wm)[(kc * 32 + k) * 32 + cq];
        }
        __syncthreads();

        #pragma unroll
        for (int k = 0; k < 32; k++) {
            float b0[8], a0[8];
            *(float4*)&b0[0] = *(const float4*)&Bs[k][tx * 8];
            *(float4*)&b0[4] = *(const float4*)&Bs[k][tx * 8 + 4];
            #pragma unroll
            for (int i = 0; i < 8; i++) a0[i] = As[ty * 8 + i][k];
            #pragma unroll
            for (int i = 0; i < 8; i++)
                #pragma unroll
                for (int j = 0; j < 8; j++)
                    acc[i * 8 + j] = fmaf(a0[i], b0[j], acc[i * 8 + j]);
        }
        __syncthreads();
    }

    float bb[8];
    *(float4*)&bb[0] = *(const float4*)&bias[tx * 8];
    *(float4*)&bb[4] = *(const float4*)&bias[tx * 8 + 4];

    #pragma unroll
    for (int i = 0; i < 8; i++) {
        int row = rowBase + ty * 8 + i;
        if (row < NN) {
            float4 o0, o1;
            o0.x = acc[i * 8 + 0] + bb[0];
            o0.y = acc[i * 8 + 1] + bb[1];
            o0.z = acc[i * 8 + 2] + bb[2];
            o0.w = acc[i * 8 + 3] + bb[3];
            o1.x = acc[i * 8 + 4] + bb[4];
            o1.y = acc[i * 8 + 5] + bb[5];
            o1.z = acc[i * 8 + 6] + bb[6];
            o1.w = acc[i * 8 + 7] + bb[7];
            if (relu) {
                o0.x = fmaxf(o0.x, 0.f); o0.y = fmaxf(o0.y, 0.f);
                o0.z = fmaxf(o0.z, 0.f); o0.w = fmaxf(o0.w, 0.f);
                o1.x = fmaxf(o1.x, 0.f); o1.y = fmaxf(o1.y, 0.f);
                o1.z = fmaxf(o1.z, 0.f); o1.w = fmaxf(o1.w, 0.f);
            }
            float4* op = reinterpret_cast<float4*>(out + row * HD + tx * 8);
            op[0] = o0;
            op[1] = o1;
        }
    }
}

// ---------------- APPNP propagation: one warp per node -----------------------
// mode 0: h0 -> hA, mode 1: hA -> hB, mode 2: hB -> hA
__global__ __launch_bounds__(256) void propagate(int mode) {
    int warp = (blockIdx.x * blockDim.x + threadIdx.x) >> 5;
    int lane = threadIdx.x & 31;
    if (warp >= NN) return;

    const float4* __restrict__ hin  = (mode == 0) ? g_h0 : ((mode == 1) ? g_hA : g_hB);
    float4* __restrict__       hout = (mode == 1) ? g_hB : g_hA;

    int beg = g_rowptr[warp];
    int end = g_rowptr[warp + 1];

    float4 acc = make_float4(0.f, 0.f, 0.f, 0.f);
    #pragma unroll 4
    for (int e = beg; e < end; e++) {
        int s = __ldg(&g_col[e]);
        float ww = __ldg(&g_w[e]);
        float4 v = hin[s * 32 + lane];
        acc.x = fmaf(ww, v.x, acc.x);
        acc.y = fmaf(ww, v.y, acc.y);
        acc.z = fmaf(ww, v.z, acc.z);
        acc.w = fmaf(ww, v.w, acc.w);
    }
    float4 z = g_h0[warp * 32 + lane];
    float4 o;
    o.x = 0.9f * acc.x + 0.1f * z.x;
    o.y = 0.9f * acc.y + 0.1f * z.y;
    o.z = 0.9f * acc.z + 0.1f * z.z;
    o.w = 0.9f * acc.w + 0.1f * z.w;
    hout[warp * 32 + lane] = o;
}

// ---------------- launch ------------------------------------------------------
extern "C" void kernel_launch(void* const* d_in, const int* in_sizes, int n_in,
                              void* d_out, int out_size) {
    const float* x  = (const float*)d_in[0];
    const void*  ei = d_in[1];
    const float* W1 = (const float*)d_in[2];
    const float* b1 = (const float*)d_in[3];
    const float* W2 = (const float*)d_in[4];
    const float* b2 = (const float*)d_in[5];
    float* out = (float*)d_out;

    void *p_h0 = nullptr, *p_hB = nullptr;
    cudaGetSymbolAddress(&p_h0, g_h0);
    cudaGetSymbolAddress(&p_hB, g_hB);

    const int T = 256;
    detect64<<<1, 32>>>((const int*)ei);
    init_deg<<<(NN + T - 1) / T, T>>>();
    hist<<<(NE + T - 1) / T, T>>>(ei);
    dinv_k<<<(NN + T - 1) / T, T>>>();
    scan1<<<(NN + 2047) / 2048, 256>>>();
    scan2<<<1, 1>>>((NN + 2047) / 2048);
    scan3<<<(NN + T - 1) / T, T>>>();
    scatter<<<(TOT + T - 1) / T, T>>>(ei);

    gemm128<<<(NN + 127) / 128, 256>>>(x, W1, b1, (float*)p_h0, 1);

    for (int t = 0; t < 10; t++) {
        int mode = (t == 0) ? 0 : ((t & 1) ? 1 : 2);
        propagate<<<(NN * 32 + T - 1) / T, T>>>(mode);
    }

    gemm128<<<(NN + 127) / 128, 256>>>((const float*)p_hB, W2, b2, out, 0);
}

// round 3
// speedup vs baseline: 1.1711x; 1.1711x over previous
#include <cuda_runtime.h>
#include <cuda_fp16.h>

#define NN 100000
#define NE 1600000
#define TOT (NE + NN)
#define HD 128

union H2U { unsigned int u; __half2 h; };

__device__ __forceinline__ unsigned int h2_to_u(__half2 h) { H2U c; c.h = h; return c.u; }
__device__ __forceinline__ __half2 u_to_h2(unsigned int u) { H2U c; c.u = u; return c.h; }

// ---------------- scratch (device globals; no allocation allowed) ------------
__device__ float4 g_h0f[NN * 32];    // fp32 h0 = relu(x@W1+b1)  (alpha term)
__device__ float4 g_hF[NN * 32];     // fp32 final h (input to GEMM2)
__device__ uint2  g_h16a[NN * 32];   // fp16 h buffers (128 halves/row = 32 uint2)
__device__ uint2  g_h16b[NN * 32];
__device__ int    g_cnt[NN];
__device__ int    g_fill[NN];
__device__ float  g_dinv[NN];
__device__ int    g_rowptr[NN + 1];
__device__ int2   g_ew[TOT];         // .x = src col, .y = float bits of weight
__device__ int    g_bsum[64];
__device__ int    g_boff[64];
__device__ int    g_is64;

// ---------------- edge dtype detection (int64 vs int32) ---------------------
__global__ void detect64(const int* ei32) {
    int lane = threadIdx.x;
    int orv = 0;
    for (int i = lane; i < 1024; i += 32) orv |= ei32[2 * i + 1];
    #pragma unroll
    for (int off = 16; off; off >>= 1) orv |= __shfl_xor_sync(0xFFFFFFFFu, orv, off);
    if (lane == 0) g_is64 = (orv == 0) ? 1 : 0;
}

__device__ __forceinline__ int edge_src(const void* ei, int e) {
    if (g_is64) return (int)((const long long*)ei)[e];
    return ((const int*)ei)[e];
}
__device__ __forceinline__ int edge_dst(const void* ei, int e) {
    if (g_is64) return (int)((const long long*)ei)[NE + e];
    return ((const int*)ei)[NE + e];
}

// ---------------- degree / normalization ------------------------------------
__global__ void init_deg() {
    int n = blockIdx.x * blockDim.x + threadIdx.x;
    if (n < NN) { g_cnt[n] = 1; g_fill[n] = 0; }  // 1 = self loop
}

__global__ void hist(const void* __restrict__ ei) {
    int e = blockIdx.x * blockDim.x + threadIdx.x;
    if (e < NE) atomicAdd(&g_cnt[edge_dst(ei, e)], 1);
}

__global__ void dinv_k() {
    int n = blockIdx.x * blockDim.x + threadIdx.x;
    if (n < NN) g_dinv[n] = rsqrtf((float)g_cnt[n]);
}

// ---------------- exclusive scan of g_cnt -> g_rowptr (3 kernels) ------------
__global__ void scan1() {
    __shared__ int sh[256];
    int tid = threadIdx.x;
    int base = blockIdx.x * 2048 + tid * 8;
    int v[8];
    int s = 0;
    #pragma unroll
    for (int i = 0; i < 8; i++) {
        int idx = base + i;
        v[i] = (idx < NN) ? g_cnt[idx] : 0;
        s += v[i];
    }
    sh[tid] = s;
    __syncthreads();
    for (int off = 1; off < 256; off <<= 1) {
        int t = (tid >= off) ? sh[tid - off] : 0;
        __syncthreads();
        sh[tid] += t;
        __syncthreads();
    }
    int run = sh[tid] - s;
    #pragma unroll
    for (int i = 0; i < 8; i++) {
        int idx = base + i;
        if (idx < NN) g_rowptr[idx] = run;
        run += v[i];
    }
    if (tid == 255) g_bsum[blockIdx.x] = sh[255];
}

__global__ void scan2(int nblocks) {
    int acc = 0;
    for (int i = 0; i < nblocks; i++) { g_boff[i] = acc; acc += g_bsum[i]; }
}

__global__ void scan3() {
    int idx = blockIdx.x * blockDim.x + threadIdx.x;
    if (idx < NN) g_rowptr[idx] += g_boff[idx >> 11];
    if (idx == 0) g_rowptr[NN] = TOT;
}

// ---------------- CSR scatter (edges + self loops) ---------------------------
__global__ void scatter(const void* __restrict__ ei) {
    int e = blockIdx.x * blockDim.x + threadIdx.x;
    if (e < NE) {
        int s = edge_src(ei, e);
        int d = edge_dst(ei, e);
        int pos = g_rowptr[d] + atomicAdd(&g_fill[d], 1);
        float ww = g_dinv[s] * g_dinv[d];
        g_ew[pos] = make_int2(s, __float_as_int(ww));
    } else if (e < TOT) {
        int n = e - NE;
        int pos = g_rowptr[n] + atomicAdd(&g_fill[n], 1);
        float di = g_dinv[n];
        g_ew[pos] = make_int2(n, __float_as_int(di * di));
    }
}

// ---------------- 128-tile fp32 SGEMM ----------------------------------------
// mode: 0 = plain (out fp32), 1 = relu + also write fp16 copy to g_h16a
__global__ __launch_bounds__(256) void gemm128(
    const float* __restrict__ X, const float* __restrict__ Wm,
    const float* __restrict__ bias, float* __restrict__ out, int mode)
{
    __shared__ float As[128][33];
    __shared__ float Bs[32][128];

    int tid = threadIdx.x;
    int tx = tid & 15;
    int ty = tid >> 4;
    int rowBase = blockIdx.x * 128;

    float acc[64];
    #pragma unroll
    for (int i = 0; i < 64; i++) acc[i] = 0.0f;

    for (int kc = 0; kc < 4; kc++) {
        #pragma unroll
        for (int l = 0; l < 4; l++) {
            int idx = tid + l * 256;
            int r  = idx >> 3;
            int kq = idx & 7;
            float4 v = make_float4(0.f, 0.f, 0.f, 0.f);
            int row = rowBase + r;
            if (row < NN)
                v = reinterpret_cast<const float4*>(X)[row * 32 + kc * 8 + kq];
            As[r][kq * 4 + 0] = v.x;
            As[r][kq * 4 + 1] = v.y;
            As[r][kq * 4 + 2] = v.z;
            As[r][kq * 4 + 3] = v.w;
        }
        #pragma unroll
        for (int l = 0; l < 4; l++) {
            int idx = tid + l * 256;
            int k  = idx >> 5;
            int cq = idx & 31;
            reinterpret_cast<float4*>(&Bs[k][0])[cq] =
                reinterpret_cast<const float4*>(Wm)[(kc * 32 + k) * 32 + cq];
        }
        __syncthreads();

        #pragma unroll
        for (int k = 0; k < 32; k++) {
            float b0[8], a0[8];
            *(float4*)&b0[0] = *(const float4*)&Bs[k][tx * 8];
            *(float4*)&b0[4] = *(const float4*)&Bs[k][tx * 8 + 4];
            #pragma unroll
            for (int i = 0; i < 8; i++) a0[i] = As[ty * 8 + i][k];
            #pragma unroll
            for (int i = 0; i < 8; i++)
                #pragma unroll
                for (int j = 0; j < 8; j++)
                    acc[i * 8 + j] = fmaf(a0[i], b0[j], acc[i * 8 + j]);
        }
        __syncthreads();
    }

    float bb[8];
    *(float4*)&bb[0] = *(const float4*)&bias[tx * 8];
    *(float4*)&bb[4] = *(const float4*)&bias[tx * 8 + 4];

    #pragma unroll
    for (int i = 0; i < 8; i++) {
        int row = rowBase + ty * 8 + i;
        if (row < NN) {
            float o[8];
            #pragma unroll
            for (int j = 0; j < 8; j++) o[j] = acc[i * 8 + j] + bb[j];
            if (mode) {
                #pragma unroll
                for (int j = 0; j < 8; j++) o[j] = fmaxf(o[j], 0.f);
                // fp16 copy for the first propagate gather
                uint2 u0, u1;
                u0.x = h2_to_u(__floats2half2_rn(o[0], o[1]));
                u0.y = h2_to_u(__floats2half2_rn(o[2], o[3]));
                u1.x = h2_to_u(__floats2half2_rn(o[4], o[5]));
                u1.y = h2_to_u(__floats2half2_rn(o[6], o[7]));
                g_h16a[row * 32 + tx * 2 + 0] = u0;
                g_h16a[row * 32 + tx * 2 + 1] = u1;
            }
            float4* op = reinterpret_cast<float4*>(out + row * HD + tx * 8);
            op[0] = *(float4*)&o[0];
            op[1] = *(float4*)&o[4];
        }
    }
}

// ---------------- APPNP propagation: one warp per node, fp16 gather ----------
// iter t: reads (t&1 ? g_h16b : g_h16a); writes g_h16{other} for t<9,
// fp32 g_hF for t==9.
__global__ __launch_bounds__(256) void propagate(int t) {
    int node = (blockIdx.x * blockDim.x + threadIdx.x) >> 5;
    int lane = threadIdx.x & 31;
    if (node >= NN) return;

    const uint2* __restrict__ hin = (t & 1) ? g_h16b : g_h16a;
    uint2* __restrict__ hout16    = (t & 1) ? g_h16a : g_h16b;

    int beg = g_rowptr[node];
    int end = g_rowptr[node + 1];

    float acc0 = 0.f, acc1 = 0.f, acc2 = 0.f, acc3 = 0.f;
    #pragma unroll 4
    for (int e = beg; e < end; e++) {
        int2 ew = __ldg(&g_ew[e]);
        float ww = __int_as_float(ew.y);
        uint2 hv = __ldg(&hin[ew.x * 32 + lane]);
        float2 f0 = __half22float2(u_to_h2(hv.x));
        float2 f1 = __half22float2(u_to_h2(hv.y));
        acc0 = fmaf(ww, f0.x, acc0);
        acc1 = fmaf(ww, f0.y, acc1);
        acc2 = fmaf(ww, f1.x, acc2);
        acc3 = fmaf(ww, f1.y, acc3);
    }
    float4 z = g_h0f[node * 32 + lane];
    float o0 = 0.9f * acc0 + 0.1f * z.x;
    float o1 = 0.9f * acc1 + 0.1f * z.y;
    float o2 = 0.9f * acc2 + 0.1f * z.z;
    float o3 = 0.9f * acc3 + 0.1f * z.w;

    if (t == 9) {
        g_hF[node * 32 + lane] = make_float4(o0, o1, o2, o3);
    } else {
        uint2 u;
        u.x = h2_to_u(__floats2half2_rn(o0, o1));
        u.y = h2_to_u(__floats2half2_rn(o2, o3));
        hout16[node * 32 + lane] = u;
    }
}

// ---------------- launch ------------------------------------------------------
extern "C" void kernel_launch(void* const* d_in, const int* in_sizes, int n_in,
                              void* d_out, int out_size) {
    const float* x  = (const float*)d_in[0];
    const void*  ei = d_in[1];
    const float* W1 = (const float*)d_in[2];
    const float* b1 = (const float*)d_in[3];
    const float* W2 = (const float*)d_in[4];
    const float* b2 = (const float*)d_in[5];
    float* out = (float*)d_out;

    void *p_h0 = nullptr, *p_hF = nullptr;
    cudaGetSymbolAddress(&p_h0, g_h0f);
    cudaGetSymbolAddress(&p_hF, g_hF);

    const int T = 256;
    detect64<<<1, 32>>>((const int*)ei);
    init_deg<<<(NN + T - 1) / T, T>>>();
    hist<<<(NE + T - 1) / T, T>>>(ei);
    dinv_k<<<(NN + T - 1) / T, T>>>();
    scan1<<<(NN + 2047) / 2048, 256>>>();
    scan2<<<1, 1>>>((NN + 2047) / 2048);
    scan3<<<(NN + T - 1) / T, T>>>();
    scatter<<<(TOT + T - 1) / T, T>>>(ei);

    gemm128<<<(NN + 127) / 128, 256>>>(x, W1, b1, (float*)p_h0, 1);

    for (int t = 0; t < 10; t++)
        propagate<<<(NN * 32 + T - 1) / T, T>>>(t);

    gemm128<<<(NN + 127) / 128, 256>>>((const float*)p_hF, W2, b2, out, 0);
}

// round 4
// speedup vs baseline: 1.3027x; 1.1124x over previous
#include <cuda_runtime.h>
#include <cuda_fp16.h>

#define NN 100000
#define NE 1600000
#define TOT (NE + NN)
#define HD 128

union H2U { unsigned int u; __half2 h; };
__device__ __forceinline__ unsigned int h2_to_u(__half2 h) { H2U c; c.h = h; return c.u; }
__device__ __forceinline__ __half2 u_to_h2(unsigned int u) { H2U c; c.u = u; return c.h; }

// ---------------- scratch (device globals; no allocation allowed) ------------
__device__ float4 g_hF[NN * 32];     // fp32 final h (input to GEMM2)
__device__ uint4  g_h0h[NN * 16];    // fp16 h0 (alpha term), 256B/row
__device__ uint4  g_h16a[NN * 16];   // fp16 ping
__device__ uint4  g_h16b[NN * 16];   // fp16 pong
__device__ int    g_cnt[NN];
__device__ int    g_fill[NN];
__device__ float  g_dinv[NN];
__device__ int    g_rowptr[NN + 1];
__device__ int2   g_ew[TOT];         // .x = src col, .y = float bits of 0.9*w
__device__ int    g_bsum[64];
__device__ int    g_is64;

// ---------------- init counters + edge dtype detection -----------------------
__global__ void initdet(const int* ei32) {
    int n = blockIdx.x * blockDim.x + threadIdx.x;
    if (n < NN) { g_cnt[n] = 1; g_fill[n] = 0; }  // 1 = self loop
    if (blockIdx.x == 0 && threadIdx.x < 32) {
        int lane = threadIdx.x;
        int orv = 0;
        for (int i = lane; i < 1024; i += 32) orv |= ei32[2 * i + 1];
        #pragma unroll
        for (int off = 16; off; off >>= 1) orv |= __shfl_xor_sync(0xFFFFFFFFu, orv, off);
        if (lane == 0) g_is64 = (orv == 0) ? 1 : 0;
    }
}

__device__ __forceinline__ int edge_src(const void* ei, int e) {
    if (g_is64) return (int)((const long long*)ei)[e];
    return ((const int*)ei)[e];
}
__device__ __forceinline__ int edge_dst(const void* ei, int e) {
    if (g_is64) return (int)((const long long*)ei)[NE + e];
    return ((const int*)ei)[NE + e];
}

__global__ void hist(const void* __restrict__ ei) {
    int e = blockIdx.x * blockDim.x + threadIdx.x;
    if (e < NE) atomicAdd(&g_cnt[edge_dst(ei, e)], 1);
}

// ---------------- scan of g_cnt -> g_rowptr (+ dinv) --------------------------
// 256 threads/block, 8 elems/thread -> 2048/block, 49 blocks.
__global__ void scan1() {
    __shared__ int sh[256];
    int tid = threadIdx.x;
    int base = blockIdx.x * 2048 + tid * 8;
    int v[8];
    int s = 0;
    #pragma unroll
    for (int i = 0; i < 8; i++) {
        int idx = base + i;
        v[i] = (idx < NN) ? g_cnt[idx] : 0;
        if (idx < NN) g_dinv[idx] = rsqrtf((float)v[i]);
        s += v[i];
    }
    sh[tid] = s;
    __syncthreads();
    for (int off = 1; off < 256; off <<= 1) {
        int t = (tid >= off) ? sh[tid - off] : 0;
        __syncthreads();
        sh[tid] += t;
        __syncthreads();
    }
    int run = sh[tid] - s;
    #pragma unroll
    for (int i = 0; i < 8; i++) {
        int idx = base + i;
        if (idx < NN) g_rowptr[idx] = run;
        run += v[i];
    }
    if (tid == 255) g_bsum[blockIdx.x] = sh[255];
}

// add cross-block offsets (2048 % 256 == 0, so all threads of a block share sblk)
__global__ void scanfix() {
    __shared__ int soff;
    int idx = blockIdx.x * blockDim.x + threadIdx.x;
    int sblk = (blockIdx.x * 256) >> 11;
    if (threadIdx.x == 0) {
        int a = 0;
        for (int i = 0; i < sblk; i++) a += g_bsum[i];
        soff = a;
    }
    __syncthreads();
    if (idx < NN) g_rowptr[idx] += soff;
    if (idx == 0) g_rowptr[NN] = TOT;
}

// ---------------- CSR scatter (edges + self loops), weights pre-scaled by 0.9
__global__ void scatter(const void* __restrict__ ei) {
    int e = blockIdx.x * blockDim.x + threadIdx.x;
    if (e < NE) {
        int s = edge_src(ei, e);
        int d = edge_dst(ei, e);
        int pos = g_rowptr[d] + atomicAdd(&g_fill[d], 1);
        float ww = 0.9f * g_dinv[s] * g_dinv[d];
        g_ew[pos] = make_int2(s, __float_as_int(ww));
    } else if (e < TOT) {
        int n = e - NE;
        int pos = g_rowptr[n] + atomicAdd(&g_fill[n], 1);
        float di = g_dinv[n];
        g_ew[pos] = make_int2(n, __float_as_int(0.9f * di * di));
    }
}

// ---------------- 128-tile fp32 SGEMM ----------------------------------------
// mode 0: plain fp32 out.  mode 1: relu, write fp16 to g_h16a AND g_h0h only.
__global__ __launch_bounds__(256) void gemm128(
    const float* __restrict__ X, const float* __restrict__ Wm,
    const float* __restrict__ bias, float* __restrict__ out, int mode)
{
    __shared__ float As[128][33];
    __shared__ float Bs[32][128];

    int tid = threadIdx.x;
    int tx = tid & 15;
    int ty = tid >> 4;
    int rowBase = blockIdx.x * 128;

    float acc[64];
    #pragma unroll
    for (int i = 0; i < 64; i++) acc[i] = 0.0f;

    for (int kc = 0; kc < 4; kc++) {
        #pragma unroll
        for (int l = 0; l < 4; l++) {
            int idx = tid + l * 256;
            int r  = idx >> 3;
            int kq = idx & 7;
            float4 v = make_float4(0.f, 0.f, 0.f, 0.f);
            int row = rowBase + r;
            if (row < NN)
                v = reinterpret_cast<const float4*>(X)[row * 32 + kc * 8 + kq];
            As[r][kq * 4 + 0] = v.x;
            As[r][kq * 4 + 1] = v.y;
            As[r][kq * 4 + 2] = v.z;
            As[r][kq * 4 + 3] = v.w;
        }
        #pragma unroll
        for (int l = 0; l < 4; l++) {
            int idx = tid + l * 256;
            int k  = idx >> 5;
            int cq = idx & 31;
            reinterpret_cast<float4*>(&Bs[k][0])[cq] =
                reinterpret_cast<const float4*>(Wm)[(kc * 32 + k) * 32 + cq];
        }
        __syncthreads();

        #pragma unroll
        for (int k = 0; k < 32; k++) {
            float b0[8], a0[8];
            *(float4*)&b0[0] = *(const float4*)&Bs[k][tx * 8];
            *(float4*)&b0[4] = *(const float4*)&Bs[k][tx * 8 + 4];
            #pragma unroll
            for (int i = 0; i < 8; i++) a0[i] = As[ty * 8 + i][k];
            #pragma unroll
            for (int i = 0; i < 8; i++)
                #pragma unroll
                for (int j = 0; j < 8; j++)
                    acc[i * 8 + j] = fmaf(a0[i], b0[j], acc[i * 8 + j]);
        }
        __syncthreads();
    }

    float bb[8];
    *(float4*)&bb[0] = *(const float4*)&bias[tx * 8];
    *(float4*)&bb[4] = *(const float4*)&bias[tx * 8 + 4];

    #pragma unroll
    for (int i = 0; i < 8; i++) {
        int row = rowBase + ty * 8 + i;
        if (row < NN) {
            float o[8];
            #pragma unroll
            for (int j = 0; j < 8; j++) o[j] = acc[i * 8 + j] + bb[j];
            if (mode) {
                #pragma unroll
                for (int j = 0; j < 8; j++) o[j] = fmaxf(o[j], 0.f);
                uint4 u;
                u.x = h2_to_u(__floats2half2_rn(o[0], o[1]));
                u.y = h2_to_u(__floats2half2_rn(o[2], o[3]));
                u.z = h2_to_u(__floats2half2_rn(o[4], o[5]));
                u.w = h2_to_u(__floats2half2_rn(o[6], o[7]));
                g_h16a[row * 16 + tx] = u;
                g_h0h[row * 16 + tx] = u;
            } else {
                float4* op = reinterpret_cast<float4*>(out + row * HD + tx * 8);
                op[0] = *(float4*)&o[0];
                op[1] = *(float4*)&o[4];
            }
        }
    }
}

// ---------------- APPNP propagation: 16 threads/node, uint4 fp16 gathers -----
__global__ __launch_bounds__(256) void propagate(int t) {
    int idx = blockIdx.x * blockDim.x + threadIdx.x;
    int node = idx >> 4;
    int lane = idx & 15;
    if (node >= NN) return;

    const uint4* __restrict__ hin = (t & 1) ? g_h16b : g_h16a;
    uint4* __restrict__ hout      = (t & 1) ? g_h16a : g_h16b;

    int beg = g_rowptr[node];
    int end = g_rowptr[node + 1];

    float a0 = 0.f, a1 = 0.f, a2 = 0.f, a3 = 0.f;
    float a4 = 0.f, a5 = 0.f, a6 = 0.f, a7 = 0.f;
    #pragma unroll 4
    for (int e = beg; e < end; e++) {
        int2 ew = __ldg(&g_ew[e]);
        float ww = __int_as_float(ew.y);
        uint4 hv = __ldg(&hin[ew.x * 16 + lane]);
        float2 f0 = __half22float2(u_to_h2(hv.x));
        float2 f1 = __half22float2(u_to_h2(hv.y));
        float2 f2 = __half22float2(u_to_h2(hv.z));
        float2 f3 = __half22float2(u_to_h2(hv.w));
        a0 = fmaf(ww, f0.x, a0); a1 = fmaf(ww, f0.y, a1);
        a2 = fmaf(ww, f1.x, a2); a3 = fmaf(ww, f1.y, a3);
        a4 = fmaf(ww, f2.x, a4); a5 = fmaf(ww, f2.y, a5);
        a6 = fmaf(ww, f3.x, a6); a7 = fmaf(ww, f3.y, a7);
    }

    uint4 zv = __ldg(&g_h0h[node * 16 + lane]);
    float2 z0 = __half22float2(u_to_h2(zv.x));
    float2 z1 = __half22float2(u_to_h2(zv.y));
    float2 z2 = __half22float2(u_to_h2(zv.z));
    float2 z3 = __half22float2(u_to_h2(zv.w));
    float o0 = a0 + 0.1f * z0.x, o1 = a1 + 0.1f * z0.y;
    float o2 = a2 + 0.1f * z1.x, o3 = a3 + 0.1f * z1.y;
    float o4 = a4 + 0.1f * z2.x, o5 = a5 + 0.1f * z2.y;
    float o6 = a6 + 0.1f * z3.x, o7 = a7 + 0.1f * z3.y;

    if (t == 9) {
        g_hF[node * 32 + lane * 2 + 0] = make_float4(o0, o1, o2, o3);
        g_hF[node * 32 + lane * 2 + 1] = make_float4(o4, o5, o6, o7);
    } else {
        uint4 u;
        u.x = h2_to_u(__floats2half2_rn(o0, o1));
        u.y = h2_to_u(__floats2half2_rn(o2, o3));
        u.z = h2_to_u(__floats2half2_rn(o4, o5));
        u.w = h2_to_u(__floats2half2_rn(o6, o7));
        hout[node * 16 + lane] = u;
    }
}

// ---------------- launch ------------------------------------------------------
extern "C" void kernel_launch(void* const* d_in, const int* in_sizes, int n_in,
                              void* d_out, int out_size) {
    const float* x  = (const float*)d_in[0];
    const void*  ei = d_in[1];
    const float* W1 = (const float*)d_in[2];
    const float* b1 = (const float*)d_in[3];
    const float* W2 = (const float*)d_in[4];
    const float* b2 = (const float*)d_in[5];
    float* out = (float*)d_out;

    void* p_hF = nullptr;
    cudaGetSymbolAddress(&p_hF, g_hF);

    const int T = 256;
    initdet<<<(NN + T - 1) / T, T>>>((const int*)ei);
    hist<<<(NE + T - 1) / T, T>>>(ei);
    scan1<<<(NN + 2047) / 2048, 256>>>();
    scanfix<<<(NN + T - 1) / T, T>>>();
    scatter<<<(TOT + T - 1) / T, T>>>(ei);

    gemm128<<<(NN + 127) / 128, 256>>>(x, W1, b1, nullptr, 1);

    for (int t = 0; t < 10; t++)
        propagate<<<(NN * 16 + T - 1) / T, T>>>(t);

    gemm128<<<(NN + 127) / 128, 256>>>((const float*)p_hF, W2, b2, out, 0);
}